// round 17
// baseline (speedup 1.0000x reference)
#include <cuda_runtime.h>

#define HID 128
#define VOCAB 28
#define N_NODES_MAX 100000
#define N_EDGES_MAX 1600000
#define FOLD_BLOCKS 32   // 28 Ep rows + b0c + Wc + scalars/y-zero

// ---- device scratch (no allocations allowed) ----
// Packed per-node histogram: 8 uint32 per node = one 32B sector.
// INVARIANT: all-zero at kernel_launch entry (zero-init at load; node phase
// re-zeroes every sector it consumes, restoring the invariant for replays).
__device__ __align__(16) unsigned g_cntp[N_NODES_MAX * 8];   // 3.2 MB
__device__ float g_Ep[VOCAB * HID];     // embed @ (w1_0 @ w2_0)
__device__ float g_b0c[HID];            // b1_0 @ w2_0 + b2_0
__device__ float g_Wc[HID];             // w1_1 @ w2_1
__device__ float g_scal[3];             // {1+eps0, 1+eps1, b1_1.w2_1 + b2_1}
__device__ float g_z1[N_NODES_MAX];     // relu(h0) . Wc per node
__device__ float g_xfall[N_NODES_MAX];  // fallback x buffer
// generation-counting grid barrier (replay-safe; proven in R12)
__device__ unsigned g_bar = 0;
__device__ volatile unsigned g_gen = 0;

#define GSYNC(PHASE, NB)                                                      \
    do {                                                                      \
        __syncthreads();                                                      \
        if (tid == 0) {                                                       \
            __threadfence();                                                  \
            if (atomicAdd(&g_bar, 1u) == (unsigned)((NB) - 1)) {              \
                g_bar = 0u;                                                   \
                __threadfence();                                              \
                g_gen = s_gen0 + (PHASE);                                     \
            } else {                                                          \
                while ((unsigned)(g_gen - s_gen0) < (unsigned)(PHASE))        \
                    __nanosleep(64);                                          \
            }                                                                 \
        }                                                                     \
        __syncthreads();                                                      \
    } while (0)

// ================= KERNEL A: fold ∥ hist → barrier → node ==================
__global__ void __launch_bounds__(256)
k_A(const int* __restrict__ src, const int* __restrict__ dst,
    const int* __restrict__ xidx, int n4, int n_edges,
    const float* __restrict__ embed, const float* __restrict__ w1_0,
    const float* __restrict__ b1_0,  const float* __restrict__ w2_0,
    const float* __restrict__ b2_0,  const float* __restrict__ w1_1,
    const float* __restrict__ b1_1,  const float* __restrict__ w2_1,
    const float* __restrict__ b2_1,  const float* __restrict__ eps0,
    const float* __restrict__ eps1,
    float* __restrict__ y_out, float* __restrict__ x_out,
    int y_len, int n_nodes)
{
    __shared__ __align__(16) float sEp[VOCAB * HID];
    __shared__ __align__(16) float sB[HID];   // fold reuses as sT pre-barrier
    __shared__ __align__(16) float sW[HID];
    __shared__ unsigned s_gen0;

    const int bid = blockIdx.x, tid = threadIdx.x;
    const int nb = gridDim.x;
    const int gsz = nb * 256;
    const int lane = tid & 31;

    if (tid == 0) s_gen0 = g_gen;   // all blocks co-resident: read before any release
    __syncthreads();

    // ---- fold duties (blocks 0..31); sB doubles as the sT staging buffer ----
    if (bid < FOLD_BLOCKS) {
        int j = tid;
        if (bid < VOCAB) {
            if (j < HID) {
                float a0 = 0.f, a1 = 0.f, a2 = 0.f, a3 = 0.f;
                #pragma unroll
                for (int m = 0; m < HID; m += 4) {
                    a0 = fmaf(embed[bid * HID + m + 0], w1_0[(m + 0) * HID + j], a0);
                    a1 = fmaf(embed[bid * HID + m + 1], w1_0[(m + 1) * HID + j], a1);
                    a2 = fmaf(embed[bid * HID + m + 2], w1_0[(m + 2) * HID + j], a2);
                    a3 = fmaf(embed[bid * HID + m + 3], w1_0[(m + 3) * HID + j], a3);
                }
                sB[j] = (a0 + a1) + (a2 + a3);
            }
            __syncthreads();
            if (j < HID) {
                float c0 = 0.f, c1 = 0.f, c2 = 0.f, c3 = 0.f;
                #pragma unroll
                for (int k = 0; k < HID; k += 4) {
                    c0 = fmaf(sB[k + 0], w2_0[(k + 0) * HID + j], c0);
                    c1 = fmaf(sB[k + 1], w2_0[(k + 1) * HID + j], c1);
                    c2 = fmaf(sB[k + 2], w2_0[(k + 2) * HID + j], c2);
                    c3 = fmaf(sB[k + 3], w2_0[(k + 3) * HID + j], c3);
                }
                g_Ep[bid * HID + j] = (c0 + c1) + (c2 + c3);
            }
        } else if (bid == VOCAB) {          // b0c = b1_0 @ w2_0 + b2_0
            if (j < HID) {
                float c0 = b2_0[j], c1 = 0.f, c2 = 0.f, c3 = 0.f;
                #pragma unroll
                for (int k = 0; k < HID; k += 4) {
                    c0 = fmaf(b1_0[k + 0], w2_0[(k + 0) * HID + j], c0);
                    c1 = fmaf(b1_0[k + 1], w2_0[(k + 1) * HID + j], c1);
                    c2 = fmaf(b1_0[k + 2], w2_0[(k + 2) * HID + j], c2);
                    c3 = fmaf(b1_0[k + 3], w2_0[(k + 3) * HID + j], c3);
                }
                g_b0c[j] = (c0 + c1) + (c2 + c3);
            }
        } else if (bid == VOCAB + 1) {      // Wc = w1_1 @ w2_1
            if (j < HID) {
                float c0 = 0.f, c1 = 0.f, c2 = 0.f, c3 = 0.f;
                #pragma unroll
                for (int k = 0; k < HID; k += 4) {
                    c0 = fmaf(w1_1[j * HID + k + 0], w2_1[k + 0], c0);
                    c1 = fmaf(w1_1[j * HID + k + 1], w2_1[k + 1], c1);
                    c2 = fmaf(w1_1[j * HID + k + 2], w2_1[k + 2], c2);
                    c3 = fmaf(w1_1[j * HID + k + 3], w2_1[k + 3], c3);
                }
                g_Wc[j] = (c0 + c1) + (c2 + c3);
            }
        } else {                            // scalars + zero y
            if (j == 0) {
                float bc = b2_1[0];
                for (int jj = 0; jj < HID; jj++) bc = fmaf(b1_1[jj], w2_1[jj], bc);
                g_scal[0] = 1.f + eps0[0];
                g_scal[1] = 1.f + eps1[0];
                g_scal[2] = bc;
            }
            for (int i = j; i < y_len; i += 256) y_out[i] = 0.f;
        }
    }

    // ---- hist: grid-stride over int4 edge groups (all blocks; balanced) ----
    for (int i = bid * 256 + tid; i < n4; i += gsz) {
        int4 s = ((const int4*)src)[i];
        int4 d = ((const int4*)dst)[i];
        int t0 = xidx[s.x], t1 = xidx[s.y], t2 = xidx[s.z], t3 = xidx[s.w];
        atomicAdd(&g_cntp[d.x * 8 + (t0 >> 2)], 1u << ((t0 & 3) * 8));
        atomicAdd(&g_cntp[d.y * 8 + (t1 >> 2)], 1u << ((t1 & 3) * 8));
        atomicAdd(&g_cntp[d.z * 8 + (t2 >> 2)], 1u << ((t2 & 3) * 8));
        atomicAdd(&g_cntp[d.w * 8 + (t3 >> 2)], 1u << ((t3 & 3) * 8));
    }
    {
        int e = n4 * 4 + bid * 256 + tid;
        if (e < n_edges) {
            int t = xidx[src[e]];
            atomicAdd(&g_cntp[dst[e] * 8 + (t >> 2)], 1u << ((t & 3) * 8));
        }
    }

    GSYNC(1, nb);

    // ---- node phase: warp per node, grid-stride ----
    for (int i = tid; i < VOCAB * HID; i += 256) sEp[i] = g_Ep[i];
    if (tid < HID) { sB[tid] = g_b0c[tid]; sW[tid] = g_Wc[tid]; }
    __syncthreads();

    float eps0p = g_scal[0], eps1p = g_scal[1], bc = g_scal[2];
    int j0 = lane * 4;
    float4 w4 = *(const float4*)&sW[j0];
    float4 b4 = *(const float4*)&sB[j0];
    int wglob = bid * 8 + (tid >> 5);
    int wstride = nb * 8;

    for (int node = wglob; node < n_nodes; node += wstride) {
        unsigned w = 0;
        if (lane < 8) {
            w = g_cntp[node * 8 + lane];    // atomics bypassed L1: fresh from L2
            g_cntp[node * 8 + lane] = 0u;   // restore all-zero invariant
        }
        int tn = xidx[node];
        unsigned wsrc = __shfl_sync(0xffffffffu, w, lane >> 2);
        unsigned cl = (wsrc >> ((lane & 3) * 8)) & 255u;
        unsigned mask = __ballot_sync(0xffffffffu, (lane < VOCAB) && cl);

        float4 acc = b4;
        {
            float4 e4 = *(const float4*)&sEp[tn * HID + j0];
            acc.x = fmaf(eps0p, e4.x, acc.x); acc.y = fmaf(eps0p, e4.y, acc.y);
            acc.z = fmaf(eps0p, e4.z, acc.z); acc.w = fmaf(eps0p, e4.w, acc.w);
        }
        while (mask) {                      // only present types (~12 avg)
            int t = __ffs(mask) - 1; mask &= mask - 1;
            float f = (float)__shfl_sync(0xffffffffu, cl, t);
            float4 e4 = *(const float4*)&sEp[t * HID + j0];
            acc.x = fmaf(f, e4.x, acc.x); acc.y = fmaf(f, e4.y, acc.y);
            acc.z = fmaf(f, e4.z, acc.z); acc.w = fmaf(f, e4.w, acc.w);
        }
        float s = fmaxf(acc.x, 0.f) * w4.x + fmaxf(acc.y, 0.f) * w4.y
                + fmaxf(acc.z, 0.f) * w4.z + fmaxf(acc.w, 0.f) * w4.w;
        #pragma unroll
        for (int o = 16; o > 0; o >>= 1) s += __shfl_xor_sync(0xffffffffu, s, o);
        if (lane == 0) {
            g_z1[node] = s;
            x_out[node] = fmaf(eps1p, s, bc);   // scatter adds on top
        }
    }
}

// ================= KERNEL B: scatter → barrier → final =====================
__global__ void __launch_bounds__(256)
k_B(const int* __restrict__ src, const int* __restrict__ dst,
    const int* __restrict__ batch,
    float* __restrict__ x_out, float* __restrict__ y_out,
    int n4, int n_edges, int n_nodes)
{
    __shared__ unsigned s_gen0;
    const int bid = blockIdx.x, tid = threadIdx.x;
    const int nb = gridDim.x;
    const int gsz = nb * 256;
    const int lane = tid & 31;

    if (tid == 0) s_gen0 = g_gen;
    __syncthreads();

    cudaGridDependencySynchronize();   // A's g_z1 / x_out init / g_gen stable

    // ---- scatter: grid-stride over int4 edge groups ----
    for (int i = bid * 256 + tid; i < n4; i += gsz) {
        int4 s = ((const int4*)src)[i];
        int4 d = ((const int4*)dst)[i];
        float z0 = g_z1[s.x], z1v = g_z1[s.y], z2 = g_z1[s.z], z3 = g_z1[s.w];
        atomicAdd(&x_out[d.x], z0);
        atomicAdd(&x_out[d.y], z1v);
        atomicAdd(&x_out[d.z], z2);
        atomicAdd(&x_out[d.w], z3);
    }
    {
        int e = n4 * 4 + bid * 256 + tid;
        if (e < n_edges) atomicAdd(&x_out[dst[e]], g_z1[src[e]]);
    }

    GSYNC(1, nb);

    // ---- final: sorted batch -> warp-segmented reduce, grid-stride ----
    for (int n0 = bid * 256; n0 < n_nodes; n0 += gsz) {
        int n = n0 + tid;
        float v = 0.f;
        int g = -1;
        if (n < n_nodes) { v = x_out[n]; g = batch[n]; }  // atomics bypassed L1
        #pragma unroll
        for (int dd = 1; dd < 32; dd <<= 1) {
            float up = __shfl_up_sync(0xffffffffu, v, dd);
            int gu = __shfl_up_sync(0xffffffffu, g, dd);
            if (lane >= dd && gu == g) v += up;
        }
        int gd = __shfl_down_sync(0xffffffffu, g, 1);
        bool last = (lane == 31) || (gd != g);
        if (n < n_nodes && last) atomicAdd(&y_out[g], v);
    }
}

extern "C" void kernel_launch(void* const* d_in, const int* in_sizes, int n_in,
                              void* d_out, int out_size) {
    const int*   x_idx    = (const int*)d_in[0];
    const int*   edge_src = (const int*)d_in[1];
    const int*   edge_dst = (const int*)d_in[2];
    const int*   batch    = (const int*)d_in[3];
    const float* embed    = (const float*)d_in[4];
    const float* eps0     = (const float*)d_in[5];
    const float* w1_0     = (const float*)d_in[6];
    const float* b1_0     = (const float*)d_in[7];
    const float* w2_0     = (const float*)d_in[8];
    const float* b2_0     = (const float*)d_in[9];
    const float* eps1     = (const float*)d_in[10];
    const float* w1_1     = (const float*)d_in[11];
    const float* b1_1     = (const float*)d_in[12];
    const float* w2_1     = (const float*)d_in[13];
    const float* b2_1     = (const float*)d_in[14];

    int n_nodes = in_sizes[0];
    int n_edges = in_sizes[1];
    if (n_nodes > N_NODES_MAX) n_nodes = N_NODES_MAX;
    if (n_edges > N_EDGES_MAX) n_edges = N_EDGES_MAX;

    float* out = (float*)d_out;
    float* y_out;
    float* x_out;
    int y_len;
    if (out_size >= n_nodes + 1) {     // (y_hat, x) concatenated, y first
        y_len = out_size - n_nodes;
        y_out = out;
        x_out = out + y_len;
    } else {
        y_len = out_size;
        y_out = out;
        x_out = g_xfall;
    }

    int n4 = n_edges >> 2;

    // Exact co-residency grids (deadlock-free by occupancy API; deterministic)
    int dev = 0, sms = 0, mA = 0, mB = 0;
    cudaGetDevice(&dev);
    cudaDeviceGetAttribute(&sms, cudaDevAttrMultiProcessorCount, dev);
    cudaOccupancyMaxActiveBlocksPerMultiprocessor(&mA, k_A, 256, 0);
    cudaOccupancyMaxActiveBlocksPerMultiprocessor(&mB, k_B, 256, 0);
    if (mA < 1) mA = 1;
    if (mB < 1) mB = 1;
    int nbA = sms * mA;
    int nbB = sms * mB;
    if (nbA < FOLD_BLOCKS + 1) nbA = FOLD_BLOCKS + 1;
    // No point exceeding the work available
    int needB = (n4 + 255) / 256;
    if (nbB > needB && needB > 0) nbB = needB;

    // Kernel A: normal launch
    k_A<<<nbA, 256>>>(edge_src, edge_dst, x_idx, n4, n_edges,
                      embed, w1_0, b1_0, w2_0, b2_0,
                      w1_1, b1_1, w2_1, b2_1, eps0, eps1,
                      y_out, x_out, y_len, n_nodes);

    // Kernel B: PDL launch (overlaps launch latency with A's tail)
    cudaLaunchAttribute attr[1];
    attr[0].id = cudaLaunchAttributeProgrammaticStreamSerialization;
    attr[0].val.programmaticStreamSerializationAllowed = 1;

    cudaLaunchConfig_t cfg = {};
    cfg.blockDim = dim3(256, 1, 1);
    cfg.gridDim = dim3((unsigned)nbB, 1, 1);
    cfg.dynamicSmemBytes = 0;
    cfg.stream = 0;
    cfg.attrs = attr;
    cfg.numAttrs = 1;
    cudaLaunchKernelEx(&cfg, k_B, edge_src, edge_dst, batch,
                       x_out, y_out, n4, n_edges, n_nodes);
}